// round 14
// baseline (speedup 1.0000x reference)
#include <cuda_runtime.h>
#include <cuda_fp16.h>

#define CCH 16
#define GSZ 300

// Quad-duplicated fp16 plane scratch: entry[i][y][x] = 128B =
//   for r in 0..3: for c in 4r..4r+3: (v00,v01),(v10,v11) half pairs
// (x+1, y+1 clamped at build). Lane r reads uint4 #2r and #2r+1.
__device__ __half g_planes_q[(size_t)3 * GSZ * GSZ * 64];   // 34.56 MB
// Pair-duplicated fp16 line scratch: entry[i][g] = 64B =
//   for c in 0..15: (v_z, v_z1) half pair. Lane r reads uint4 #r.
__device__ __half g_lines_q[3 * GSZ * 32];                  // 115 KB

// ---------------------------------------------------------------------------
// Merged build. Single kernel => 2 launches total (ncu -s 5 => sampler).
// ---------------------------------------------------------------------------
__global__ void build_all_kernel(const float* __restrict__ planes,
                                 const float* __restrict__ lines) {
    int idx = blockIdx.x * blockDim.x + threadIdx.x;
    const int NP = 3 * GSZ * GSZ;
    if (idx < NP) {
        int x  = idx % GSZ;
        int yi = idx / GSZ;
        int y  = yi % GSZ;
        int i  = yi / GSZ;
        int x1 = min(x + 1, GSZ - 1);
        int y1 = min(y + 1, GSZ - 1);

        const float* P = planes + (size_t)i * CCH * GSZ * GSZ;
        __half buf[64];
#pragma unroll
        for (int c = 0; c < CCH; c++) {
            const float* pc = P + (size_t)c * GSZ * GSZ;
            buf[c * 4 + 0] = __float2half_rn(__ldg(pc + y  * GSZ + x));
            buf[c * 4 + 1] = __float2half_rn(__ldg(pc + y  * GSZ + x1));
            buf[c * 4 + 2] = __float2half_rn(__ldg(pc + y1 * GSZ + x));
            buf[c * 4 + 3] = __float2half_rn(__ldg(pc + y1 * GSZ + x1));
        }
        uint4* dst = reinterpret_cast<uint4*>(g_planes_q + (size_t)idx * 64);
        const uint4* sp = reinterpret_cast<const uint4*>(buf);
#pragma unroll
        for (int k = 0; k < 8; k++) dst[k] = sp[k];
    } else if (idx < NP + 3 * GSZ) {
        int li = idx - NP;
        int g  = li % GSZ;
        int i  = li / GSZ;
        int g1 = min(g + 1, GSZ - 1);

        __half buf[32];
#pragma unroll
        for (int c = 0; c < CCH; c++) {
            buf[c * 2 + 0] = __float2half_rn(__ldg(lines + ((size_t)i * CCH + c) * GSZ + g));
            buf[c * 2 + 1] = __float2half_rn(__ldg(lines + ((size_t)i * CCH + c) * GSZ + g1));
        }
        uint4* dst = reinterpret_cast<uint4*>(g_lines_q + (size_t)li * 32);
        const uint4* sp = reinterpret_cast<const uint4*>(buf);
#pragma unroll
        for (int k = 0; k < 4; k++) dst[k] = sp[k];
    }
}

__device__ __forceinline__ float2 h2f(unsigned int u) {
    __half2 h = *reinterpret_cast<const __half2*>(&u);
    return __half22float2(h);
}

// ---------------------------------------------------------------------------
// Sampler: 4 lanes/point (lane = p*4 + r), 8 points/warp.
// FRONT-BATCHED: all 9 gather LDG.128 issued before any interpolation math
// (MLP ~9 to hide L2-hit latency), then all math, then all stores.
// ---------------------------------------------------------------------------
__global__ __launch_bounds__(256) void vm_sample_kernel(
        const float* __restrict__ xyz, float* __restrict__ out, int N) {
    int warpGlobal = (blockIdx.x * blockDim.x + threadIdx.x) >> 5;
    int lane = threadIdx.x & 31;
    int p = lane >> 2;          // point within warp (0..7)
    int r = lane & 3;           // channel quad (0..3)
    int base = warpGlobal * 8;
    if (base >= N) return;

    // Coalesced coord fetch: first 24 lanes read xyz[base*3 .. base*3+23]
    float v = 0.0f;
    {
        long long gi = (long long)base * 3 + lane;
        if (lane < 24 && gi < (long long)N * 3)
            v = __ldg(xyz + gi);
    }
    float c0 = __shfl_sync(0xffffffffu, v, p * 3 + 0);
    float c1 = __shfl_sync(0xffffffffu, v, p * 3 + 1);
    float c2 = __shfl_sync(0xffffffffu, v, p * 3 + 2);

    int n = base + p;
    if (n >= N) return;

    float coords[3] = {c0, c1, c2};
    int   i0[3];
    float w[3];
#pragma unroll
    for (int d = 0; d < 3; d++) {
        float x  = (coords[d] + 1.0f) * 0.5f * (float)(GSZ - 1);
        float xf = floorf(x);
        xf = fminf(fmaxf(xf, 0.0f), (float)(GSZ - 1));
        i0[d] = (int)xf;
        w[d]  = x - xf;
    }

    // matMode = ((1,2),(0,2),(0,1))
    const int ma[3] = {1, 0, 0};
    const int mb[3] = {2, 2, 1};

    // ---- Phase 1: issue ALL gathers --------------------------------------
    uint4 qa[3], qb[3], ql[3];
#pragma unroll
    for (int i = 0; i < 3; i++) {
        int x0 = i0[ma[i]];
        int y0 = i0[mb[i]];
        int z0 = i0[i];
        int entry  = (i * (GSZ * GSZ) + y0 * GSZ + x0) * 64;   // halves
        int lentry = (i * GSZ + z0) * 32;                      // halves
        const uint4* q = reinterpret_cast<const uint4*>(g_planes_q + entry);
        qa[i] = q[2 * r];
        qb[i] = q[2 * r + 1];
        ql[i] = reinterpret_cast<const uint4*>(g_lines_q + lentry)[r];
    }

    // ---- Phase 2: math + stores ------------------------------------------
    int r4 = r * 4;
#pragma unroll
    for (int i = 0; i < 3; i++) {
        float wx = w[ma[i]], wy = w[mb[i]], wz = w[i];

        float w00 = (1.0f - wx) * (1.0f - wy);
        float w01 = wx * (1.0f - wy);
        float w10 = (1.0f - wx) * wy;
        float w11 = wx * wy;
        float one_wz = 1.0f - wz;

        float2 a01 = h2f(qa[i].x), a23 = h2f(qa[i].y);
        float2 b01 = h2f(qa[i].z), b23 = h2f(qa[i].w);
        float2 e01 = h2f(qb[i].x), e23 = h2f(qb[i].y);
        float2 f01 = h2f(qb[i].z), f23 = h2f(qb[i].w);

        float4 acc;
        acc.x = a01.x * w00 + a01.y * w01 + a23.x * w10 + a23.y * w11;
        acc.y = b01.x * w00 + b01.y * w01 + b23.x * w10 + b23.y * w11;
        acc.z = e01.x * w00 + e01.y * w01 + e23.x * w10 + e23.y * w11;
        acc.w = f01.x * w00 + f01.y * w01 + f23.x * w10 + f23.y * w11;

        float2 l0p = h2f(ql[i].x);
        float2 l1p = h2f(ql[i].y);
        float2 l2p = h2f(ql[i].z);
        float2 l3p = h2f(ql[i].w);

        float4 lv;
        lv.x = l0p.x * one_wz + l0p.y * wz;
        lv.y = l1p.x * one_wz + l1p.y * wz;
        lv.z = l2p.x * one_wz + l2p.y * wz;
        lv.w = l3p.x * one_wz + l3p.y * wz;

        float* o = out + ((size_t)(i * CCH + r4) * N + n);
        o[0 * (size_t)N] = acc.x * lv.x;
        o[1 * (size_t)N] = acc.y * lv.y;
        o[2 * (size_t)N] = acc.z * lv.z;
        o[3 * (size_t)N] = acc.w * lv.w;
    }
}

extern "C" void kernel_launch(void* const* d_in, const int* in_sizes, int n_in,
                              void* d_out, int out_size) {
    const float* xyz    = (const float*)d_in[0];
    const float* planes = (const float*)d_in[1];
    const float* lines  = (const float*)d_in[2];
    float* out = (float*)d_out;

    int N = in_sizes[0] / 3;

    {
        int total = 3 * GSZ * GSZ + 3 * GSZ;
        int threads = 256;
        build_all_kernel<<<(total + threads - 1) / threads, threads>>>(planes, lines);
    }
    {
        long long totalThreads = (long long)((N + 7) / 8) * 32;
        int threads = 256;
        long long blocks = (totalThreads + threads - 1) / threads;
        vm_sample_kernel<<<(int)blocks, threads>>>(xyz, out, N);
    }
}

// round 15
// speedup vs baseline: 1.0255x; 1.0255x over previous
#include <cuda_runtime.h>
#include <cuda_fp16.h>

#define CCH 16
#define GSZ 300

// Quad-duplicated fp16 plane scratch: entry[i][y][x] = 128B =
//   for r in 0..3: for c in 4r..4r+3: (v00,v01),(v10,v11) half pairs
// (x+1, y+1 clamped at build). Lane r reads uint4 #2r and #2r+1.
__device__ __half g_planes_q[(size_t)3 * GSZ * GSZ * 64];   // 34.56 MB
// Lines: channel-innermost fp32 (R10 winner config).
__device__ float  g_lines_t[3 * GSZ * CCH];                 // 57.6 KB

// ---------------------------------------------------------------------------
// Merged build. Single kernel => 2 launches total (ncu -s 5 => sampler).
// ---------------------------------------------------------------------------
__global__ void build_all_kernel(const float* __restrict__ planes,
                                 const float* __restrict__ lines) {
    int idx = blockIdx.x * blockDim.x + threadIdx.x;
    const int NP = 3 * GSZ * GSZ;
    if (idx < NP) {
        int x  = idx % GSZ;
        int yi = idx / GSZ;
        int y  = yi % GSZ;
        int i  = yi / GSZ;
        int x1 = min(x + 1, GSZ - 1);
        int y1 = min(y + 1, GSZ - 1);

        const float* P = planes + (size_t)i * CCH * GSZ * GSZ;
        __half buf[64];
#pragma unroll
        for (int c = 0; c < CCH; c++) {
            const float* pc = P + (size_t)c * GSZ * GSZ;
            buf[c * 4 + 0] = __float2half_rn(__ldg(pc + y  * GSZ + x));
            buf[c * 4 + 1] = __float2half_rn(__ldg(pc + y  * GSZ + x1));
            buf[c * 4 + 2] = __float2half_rn(__ldg(pc + y1 * GSZ + x));
            buf[c * 4 + 3] = __float2half_rn(__ldg(pc + y1 * GSZ + x1));
        }
        uint4* dst = reinterpret_cast<uint4*>(g_planes_q + (size_t)idx * 64);
        const uint4* sp = reinterpret_cast<const uint4*>(buf);
#pragma unroll
        for (int k = 0; k < 8; k++) dst[k] = sp[k];
    } else if (idx < NP + 3 * GSZ) {
        int li = idx - NP;
        int g = li % GSZ;
        int i = li / GSZ;

        float buf[CCH];
#pragma unroll
        for (int c = 0; c < CCH; c++)
            buf[c] = __ldg(lines + ((size_t)i * CCH + c) * GSZ + g);

        float4* dst = reinterpret_cast<float4*>(g_lines_t + (size_t)li * CCH);
#pragma unroll
        for (int c4 = 0; c4 < CCH / 4; c4++)
            dst[c4] = make_float4(buf[4 * c4 + 0], buf[4 * c4 + 1],
                                  buf[4 * c4 + 2], buf[4 * c4 + 3]);
    }
}

__device__ __forceinline__ float2 h2f(unsigned int u) {
    __half2 h = *reinterpret_cast<const __half2*>(&u);
    return __half22float2(h);
}

// ---------------------------------------------------------------------------
// Sampler (R10 structure): 4 lanes/point (lane = p*4 + r), 8 points/warp.
// Per mode: one 128B quad-entry (2 x uint4 LDG.128, same line) + 2 fp32
// float4 line loads. Interpolation fp32.
// NEW: streaming hints — __ldcs on xyz (read-once), __stcs on output
// (write-once) so the 384MB output stream doesn't evict the 34.5MB plane
// working set from L2.
// ---------------------------------------------------------------------------
__global__ __launch_bounds__(256) void vm_sample_kernel(
        const float* __restrict__ xyz, float* __restrict__ out, int N) {
    int warpGlobal = (blockIdx.x * blockDim.x + threadIdx.x) >> 5;
    int lane = threadIdx.x & 31;
    int p = lane >> 2;          // point within warp (0..7)
    int r = lane & 3;           // channel quad (0..3)
    int base = warpGlobal * 8;
    if (base >= N) return;

    // Coalesced coord fetch: first 24 lanes read xyz[base*3 .. base*3+23]
    float v = 0.0f;
    {
        long long gi = (long long)base * 3 + lane;
        if (lane < 24 && gi < (long long)N * 3)
            v = __ldcs(xyz + gi);
    }
    float c0 = __shfl_sync(0xffffffffu, v, p * 3 + 0);
    float c1 = __shfl_sync(0xffffffffu, v, p * 3 + 1);
    float c2 = __shfl_sync(0xffffffffu, v, p * 3 + 2);

    int n = base + p;
    if (n >= N) return;

    float coords[3] = {c0, c1, c2};
    int   i0[3], i1[3];
    float w[3];
#pragma unroll
    for (int d = 0; d < 3; d++) {
        float x  = (coords[d] + 1.0f) * 0.5f * (float)(GSZ - 1);
        float xf = floorf(x);
        xf = fminf(fmaxf(xf, 0.0f), (float)(GSZ - 1));
        i0[d] = (int)xf;
        i1[d] = min(i0[d] + 1, GSZ - 1);
        w[d]  = x - xf;
    }

    // matMode = ((1,2),(0,2),(0,1))
    const int ma[3] = {1, 0, 0};
    const int mb[3] = {2, 2, 1};

    int r4 = r * 4;

#pragma unroll
    for (int i = 0; i < 3; i++) {
        int a = ma[i], b = mb[i];
        int x0 = i0[a];
        int y0 = i0[b];
        int z0 = i0[i], z1 = i1[i];
        float wx = w[a], wy = w[b], wz = w[i];

        float w00 = (1.0f - wx) * (1.0f - wy);
        float w01 = wx * (1.0f - wy);
        float w10 = (1.0f - wx) * wy;
        float w11 = wx * wy;
        float one_wz = 1.0f - wz;

        // Plane: one 128B quad-entry, lane r reads uint4 #2r, #2r+1.
        int entry = (i * (GSZ * GSZ) + y0 * GSZ + x0) * 64;   // halves
        const uint4* q = reinterpret_cast<const uint4*>(g_planes_q + entry);
        uint4 qa = q[2 * r];       // ch 4r, 4r+1
        uint4 qb = q[2 * r + 1];   // ch 4r+2, 4r+3

        float2 a01 = h2f(qa.x), a23 = h2f(qa.y);
        float2 b01 = h2f(qa.z), b23 = h2f(qa.w);
        float2 e01 = h2f(qb.x), e23 = h2f(qb.y);
        float2 f01 = h2f(qb.z), f23 = h2f(qb.w);

        float4 acc;
        acc.x = a01.x * w00 + a01.y * w01 + a23.x * w10 + a23.y * w11;
        acc.y = b01.x * w00 + b01.y * w01 + b23.x * w10 + b23.y * w11;
        acc.z = e01.x * w00 + e01.y * w01 + e23.x * w10 + e23.y * w11;
        acc.w = f01.x * w00 + f01.y * w01 + f23.x * w10 + f23.y * w11;

        // Lines: fp32, 32-bit offsets.
        int lineBase = i * (GSZ * CCH);
        float4 E = *reinterpret_cast<const float4*>(g_lines_t + lineBase + z0 * CCH + r4);
        float4 F = *reinterpret_cast<const float4*>(g_lines_t + lineBase + z1 * CCH + r4);
        float4 lv;
        lv.x = E.x * one_wz + F.x * wz;
        lv.y = E.y * one_wz + F.y * wz;
        lv.z = E.z * one_wz + F.z * wz;
        lv.w = E.w * one_wz + F.w * wz;

        // Streaming (evict-first) stores: output is never re-read.
        float* o = out + ((size_t)(i * CCH + r4) * N + n);
        __stcs(o + 0 * (size_t)N, acc.x * lv.x);
        __stcs(o + 1 * (size_t)N, acc.y * lv.y);
        __stcs(o + 2 * (size_t)N, acc.z * lv.z);
        __stcs(o + 3 * (size_t)N, acc.w * lv.w);
    }
}

extern "C" void kernel_launch(void* const* d_in, const int* in_sizes, int n_in,
                              void* d_out, int out_size) {
    const float* xyz    = (const float*)d_in[0];
    const float* planes = (const float*)d_in[1];
    const float* lines  = (const float*)d_in[2];
    float* out = (float*)d_out;

    int N = in_sizes[0] / 3;

    // Max-L1 carveout (no smem used by either kernel). Host-side attr, not a
    // stream op — safe under graph capture; idempotent across calls.
    static bool attrs_set = false;
    if (!attrs_set) {
        cudaFuncSetAttribute(vm_sample_kernel,
                             cudaFuncAttributePreferredSharedMemoryCarveout, 0);
        cudaFuncSetAttribute(build_all_kernel,
                             cudaFuncAttributePreferredSharedMemoryCarveout, 0);
        attrs_set = true;
    }

    {
        int total = 3 * GSZ * GSZ + 3 * GSZ;
        int threads = 256;
        build_all_kernel<<<(total + threads - 1) / threads, threads>>>(planes, lines);
    }
    {
        long long totalThreads = (long long)((N + 7) / 8) * 32;
        int threads = 256;
        long long blocks = (totalThreads + threads - 1) / threads;
        vm_sample_kernel<<<(int)blocks, threads>>>(xyz, out, N);
    }
}

// round 16
// speedup vs baseline: 1.1832x; 1.1537x over previous
#include <cuda_runtime.h>
#include <cuda_fp16.h>

#define CCH 16
#define GSZ 300

// Quad-duplicated fp16 plane scratch: entry[i][y][x] = 128B =
//   for r in 0..3: for c in 4r..4r+3: (v00,v01),(v10,v11) half pairs
// (x+1, y+1 clamped at build). Lane r reads uint4 #2r and #2r+1.
__device__ __half g_planes_q[(size_t)3 * GSZ * GSZ * 64];   // 34.56 MB
// Pair-duplicated fp16 line scratch: entry[i][g] = 64B =
//   for c in 0..15: (v_z, v_z1) half pair. Lane r reads uint4 #r.
__device__ __half g_lines_q[3 * GSZ * 32];                  // 115 KB

// ---------------------------------------------------------------------------
// Merged build. Single kernel => 2 launches total (ncu -s 5 => sampler).
// ---------------------------------------------------------------------------
__global__ void build_all_kernel(const float* __restrict__ planes,
                                 const float* __restrict__ lines) {
    int idx = blockIdx.x * blockDim.x + threadIdx.x;
    const int NP = 3 * GSZ * GSZ;
    if (idx < NP) {
        int x  = idx % GSZ;
        int yi = idx / GSZ;
        int y  = yi % GSZ;
        int i  = yi / GSZ;
        int x1 = min(x + 1, GSZ - 1);
        int y1 = min(y + 1, GSZ - 1);

        const float* P = planes + (size_t)i * CCH * GSZ * GSZ;
        __half buf[64];
#pragma unroll
        for (int c = 0; c < CCH; c++) {
            const float* pc = P + (size_t)c * GSZ * GSZ;
            buf[c * 4 + 0] = __float2half_rn(__ldg(pc + y  * GSZ + x));
            buf[c * 4 + 1] = __float2half_rn(__ldg(pc + y  * GSZ + x1));
            buf[c * 4 + 2] = __float2half_rn(__ldg(pc + y1 * GSZ + x));
            buf[c * 4 + 3] = __float2half_rn(__ldg(pc + y1 * GSZ + x1));
        }
        uint4* dst = reinterpret_cast<uint4*>(g_planes_q + (size_t)idx * 64);
        const uint4* sp = reinterpret_cast<const uint4*>(buf);
#pragma unroll
        for (int k = 0; k < 8; k++) dst[k] = sp[k];
    } else if (idx < NP + 3 * GSZ) {
        int li = idx - NP;
        int g  = li % GSZ;
        int i  = li / GSZ;
        int g1 = min(g + 1, GSZ - 1);

        __half buf[32];
#pragma unroll
        for (int c = 0; c < CCH; c++) {
            buf[c * 2 + 0] = __float2half_rn(__ldg(lines + ((size_t)i * CCH + c) * GSZ + g));
            buf[c * 2 + 1] = __float2half_rn(__ldg(lines + ((size_t)i * CCH + c) * GSZ + g1));
        }
        uint4* dst = reinterpret_cast<uint4*>(g_lines_q + (size_t)li * 32);
        const uint4* sp = reinterpret_cast<const uint4*>(buf);
#pragma unroll
        for (int k = 0; k < 4; k++) dst[k] = sp[k];
    }
}

__device__ __forceinline__ float2 h2f(unsigned int u) {
    __half2 h = *reinterpret_cast<const __half2*>(&u);
    return __half22float2(h);
}

// ---------------------------------------------------------------------------
// Sampler: 4 lanes per POINT-PAIR (lane = q*4 + r), 16 points/warp.
// Thread handles points (n0, n0+1): per mode 6 front-batched gather LDG.128
// (MLP 6), then math, then 4 STG.64 (float2 per channel) -> store wavefronts
// halved to 3/pt and store instructions halved.
// ---------------------------------------------------------------------------
__global__ __launch_bounds__(256) void vm_sample_kernel(
        const float* __restrict__ xyz, float* __restrict__ out, int N) {
    int warpGlobal = (blockIdx.x * blockDim.x + threadIdx.x) >> 5;
    int lane = threadIdx.x & 31;
    int q = lane >> 2;          // point pair within warp (0..7)
    int r = lane & 3;           // channel quad (0..3)
    int base = warpGlobal * 16;
    int n0 = base + 2 * q;
    if (n0 >= N) return;
    bool has1 = (n0 + 1) < N;

    // Per-thread coord fetch: 3 x float2 (8B aligned: n0 even).
    const float2* xy2 = reinterpret_cast<const float2*>(xyz) + (size_t)n0 * 3 / 2;
    float2 ab = __ldg(xy2 + 0);   // pt0: c0, c1
    float2 cd = __ldg(xy2 + 1);   // pt0: c2 | pt1: c0
    float2 ef = has1 ? __ldg(xy2 + 2) : make_float2(0.f, 0.f);  // pt1: c1, c2

    float crd0[3] = {ab.x, ab.y, cd.x};
    float crd1[3] = {has1 ? cd.y : 0.f, ef.x, ef.y};

    int   i00[3], i01[3];
    float w0[3], w1[3];
#pragma unroll
    for (int d = 0; d < 3; d++) {
        float x  = (crd0[d] + 1.0f) * 0.5f * (float)(GSZ - 1);
        float xf = floorf(x);
        xf = fminf(fmaxf(xf, 0.0f), (float)(GSZ - 1));
        i00[d] = (int)xf;
        w0[d]  = x - xf;
        x  = (crd1[d] + 1.0f) * 0.5f * (float)(GSZ - 1);
        xf = floorf(x);
        xf = fminf(fmaxf(xf, 0.0f), (float)(GSZ - 1));
        i01[d] = (int)xf;
        w1[d]  = x - xf;
    }

    // matMode = ((1,2),(0,2),(0,1))
    const int ma[3] = {1, 0, 0};
    const int mb[3] = {2, 2, 1};

#pragma unroll
    for (int i = 0; i < 3; i++) {
        int a = ma[i], b = mb[i];

        // ---- front-batched gathers for BOTH points (MLP 6) ----
        int e0 = (i * (GSZ * GSZ) + i00[b] * GSZ + i00[a]) * 64;
        int e1 = (i * (GSZ * GSZ) + i01[b] * GSZ + i01[a]) * 64;
        int l0 = (i * GSZ + i00[i]) * 32;
        int l1 = (i * GSZ + i01[i]) * 32;

        const uint4* q0 = reinterpret_cast<const uint4*>(g_planes_q + e0);
        const uint4* q1 = reinterpret_cast<const uint4*>(g_planes_q + e1);
        uint4 qa0 = q0[2 * r];
        uint4 qb0 = q0[2 * r + 1];
        uint4 qa1 = q1[2 * r];
        uint4 qb1 = q1[2 * r + 1];
        uint4 ql0 = reinterpret_cast<const uint4*>(g_lines_q + l0)[r];
        uint4 ql1 = reinterpret_cast<const uint4*>(g_lines_q + l1)[r];

        // ---- math pt0 ----
        float wx = w0[a], wy = w0[b], wz = w0[i];
        float w00 = (1.0f - wx) * (1.0f - wy);
        float w01 = wx * (1.0f - wy);
        float w10 = (1.0f - wx) * wy;
        float w11 = wx * wy;
        float onez = 1.0f - wz;

        float2 a01 = h2f(qa0.x), a23 = h2f(qa0.y);
        float2 b01 = h2f(qa0.z), b23 = h2f(qa0.w);
        float2 e01 = h2f(qb0.x), e23 = h2f(qb0.y);
        float2 f01 = h2f(qb0.z), f23 = h2f(qb0.w);
        float4 r0;
        r0.x = a01.x * w00 + a01.y * w01 + a23.x * w10 + a23.y * w11;
        r0.y = b01.x * w00 + b01.y * w01 + b23.x * w10 + b23.y * w11;
        r0.z = e01.x * w00 + e01.y * w01 + e23.x * w10 + e23.y * w11;
        r0.w = f01.x * w00 + f01.y * w01 + f23.x * w10 + f23.y * w11;
        float2 p0 = h2f(ql0.x), p1 = h2f(ql0.y), p2 = h2f(ql0.z), p3 = h2f(ql0.w);
        r0.x *= p0.x * onez + p0.y * wz;
        r0.y *= p1.x * onez + p1.y * wz;
        r0.z *= p2.x * onez + p2.y * wz;
        r0.w *= p3.x * onez + p3.y * wz;

        // ---- math pt1 ----
        wx = w1[a]; wy = w1[b]; wz = w1[i];
        w00 = (1.0f - wx) * (1.0f - wy);
        w01 = wx * (1.0f - wy);
        w10 = (1.0f - wx) * wy;
        w11 = wx * wy;
        onez = 1.0f - wz;

        a01 = h2f(qa1.x); a23 = h2f(qa1.y);
        b01 = h2f(qa1.z); b23 = h2f(qa1.w);
        e01 = h2f(qb1.x); e23 = h2f(qb1.y);
        f01 = h2f(qb1.z); f23 = h2f(qb1.w);
        float4 r1;
        r1.x = a01.x * w00 + a01.y * w01 + a23.x * w10 + a23.y * w11;
        r1.y = b01.x * w00 + b01.y * w01 + b23.x * w10 + b23.y * w11;
        r1.z = e01.x * w00 + e01.y * w01 + e23.x * w10 + e23.y * w11;
        r1.w = f01.x * w00 + f01.y * w01 + f23.x * w10 + f23.y * w11;
        p0 = h2f(ql1.x); p1 = h2f(ql1.y); p2 = h2f(ql1.z); p3 = h2f(ql1.w);
        r1.x *= p0.x * onez + p0.y * wz;
        r1.y *= p1.x * onez + p1.y * wz;
        r1.z *= p2.x * onez + p2.y * wz;
        r1.w *= p3.x * onez + p3.y * wz;

        // ---- paired stores: float2 (pt0, pt1) per channel ----
        int cbase = i * CCH + 4 * r;
        if (has1) {
            float2* o = reinterpret_cast<float2*>(out + ((size_t)cbase * N + n0));
            size_t stride2 = (size_t)N / 2;   // N even when has1 along full pairs
            // N may be odd in general; fall back per-channel address math:
            o = reinterpret_cast<float2*>(out + ((size_t)cbase * N + n0));
            reinterpret_cast<float2*>(out + ((size_t)(cbase + 0) * N + n0))[0] = make_float2(r0.x, r1.x);
            reinterpret_cast<float2*>(out + ((size_t)(cbase + 1) * N + n0))[0] = make_float2(r0.y, r1.y);
            reinterpret_cast<float2*>(out + ((size_t)(cbase + 2) * N + n0))[0] = make_float2(r0.z, r1.z);
            reinterpret_cast<float2*>(out + ((size_t)(cbase + 3) * N + n0))[0] = make_float2(r0.w, r1.w);
            (void)stride2; (void)o;
        } else {
            out[(size_t)(cbase + 0) * N + n0] = r0.x;
            out[(size_t)(cbase + 1) * N + n0] = r0.y;
            out[(size_t)(cbase + 2) * N + n0] = r0.z;
            out[(size_t)(cbase + 3) * N + n0] = r0.w;
        }
    }
}

extern "C" void kernel_launch(void* const* d_in, const int* in_sizes, int n_in,
                              void* d_out, int out_size) {
    const float* xyz    = (const float*)d_in[0];
    const float* planes = (const float*)d_in[1];
    const float* lines  = (const float*)d_in[2];
    float* out = (float*)d_out;

    int N = in_sizes[0] / 3;

    {
        int total = 3 * GSZ * GSZ + 3 * GSZ;
        int threads = 256;
        build_all_kernel<<<(total + threads - 1) / threads, threads>>>(planes, lines);
    }
    {
        // 2 points per thread, 16 points per warp
        long long totalThreads = (long long)((N + 15) / 16) * 32;
        int threads = 256;
        long long blocks = (totalThreads + threads - 1) / threads;
        vm_sample_kernel<<<(int)blocks, threads>>>(xyz, out, N);
    }
}